// round 2
// baseline (speedup 1.0000x reference)
#include <cuda_runtime.h>
#include <cuda_bf16.h>

// RayCastLayer on sm_100a.
// x: [2048, 361] fp32 (32*64 planes of 19x19), weight: [2,18],
// out[bc][p] = sum_{r in 8 dirs} sum_{d=1..18} x[bc][p + dir_r*d] * w[group(r)][d-1]
// with taps falling off the board dropped.
//
// Strategy: 8 planes per block, plane tile transposed into smem as float4 pairs
// so each tap is 2x LDS.128 feeding 8 outputs; geometry is computed with
// compile-time-constant offsets per (direction, distance), fully unrolled.

#define BOARD 19
#define NPOS 361            // 19*19
#define MAXD 18
#define PLANES_PER_BLOCK 8
#define THREADS 384

__global__ __launch_bounds__(THREADS, 2)
void raycast_kernel(const float* __restrict__ x,
                    const float* __restrict__ weight,
                    float* __restrict__ out,
                    int nplanes)
{
    __shared__ float4 s0[NPOS];   // planes g0+0..3, indexed by position
    __shared__ float4 s1[NPOS];   // planes g0+4..7
    __shared__ float  sw[2 * MAXD];

    const int tid = threadIdx.x;
    const int g0  = blockIdx.x * PLANES_PER_BLOCK;

    // ---- load 8 planes, transposing to [position][plane] layout ----
    // i = j*NPOS + p : coalesced global reads per plane, conflict-free STS.
    float* s0f = reinterpret_cast<float*>(s0);
    float* s1f = reinterpret_cast<float*>(s1);
    #pragma unroll
    for (int i = tid; i < PLANES_PER_BLOCK * NPOS; i += THREADS) {
        const int j = i / NPOS;          // plane within group (0..7)
        const int p = i - j * NPOS;      // position
        const int gp = g0 + j;
        float v = (gp < nplanes) ? x[gp * NPOS + p] : 0.0f;
        if (j < 4) s0f[p * 4 + j]       = v;
        else       s1f[p * 4 + (j - 4)] = v;
    }
    if (tid < 2 * MAXD) sw[tid] = weight[tid];
    __syncthreads();

    if (tid < NPOS) {
        const int p  = tid;
        const int yy = p / BOARD;
        const int xx = p - yy * BOARD;

        float4 a0 = make_float4(0.f, 0.f, 0.f, 0.f);
        float4 a1 = make_float4(0.f, 0.f, 0.f, 0.f);

        #pragma unroll
        for (int d = 1; d <= MAXD; d++) {
            const float wl = sw[d - 1];          // line weight for this distance
            const float wd = sw[MAXD + d - 1];   // diagonal weight

            const int offV = BOARD * d;          // vertical step (compile-time per d)
            const int offDm = offV - d;          // diag with -x
            const int offDp = offV + d;          // diag with +x

            // helper macro: accumulate one tap if valid
            #define TAP(COND, QOFF, W)                                   \
                if (COND) {                                              \
                    const int q = p + (QOFF);                            \
                    const float4 v0 = s0[q];                             \
                    const float4 v1 = s1[q];                             \
                    a0.x = fmaf(v0.x, (W), a0.x);                        \
                    a0.y = fmaf(v0.y, (W), a0.y);                        \
                    a0.z = fmaf(v0.z, (W), a0.z);                        \
                    a0.w = fmaf(v0.w, (W), a0.w);                        \
                    a1.x = fmaf(v1.x, (W), a1.x);                        \
                    a1.y = fmaf(v1.y, (W), a1.y);                        \
                    a1.z = fmaf(v1.z, (W), a1.z);                        \
                    a1.w = fmaf(v1.w, (W), a1.w);                        \
                }

            const bool vu = (yy - d >= 0);
            const bool vd = (yy + d < BOARD);
            const bool vl = (xx - d >= 0);
            const bool vr = (xx + d < BOARD);

            // dirs 0..3 (lines): (-1,0),(1,0),(0,-1),(0,1)
            TAP(vu,        -offV,  wl)
            TAP(vd,        +offV,  wl)
            TAP(vl,        -d,     wl)
            TAP(vr,        +d,     wl)
            // dirs 4..7 (diagonals): (-1,-1),(-1,1),(1,-1),(1,1)
            TAP(vu && vl,  -offDp, wd)
            TAP(vu && vr,  -offDm, wd)
            TAP(vd && vl,  +offDm, wd)
            TAP(vd && vr,  +offDp, wd)
            #undef TAP
        }

        // ---- write 8 planes out, coalesced per plane ----
        #pragma unroll
        for (int j = 0; j < PLANES_PER_BLOCK; j++) {
            const int gp = g0 + j;
            if (gp < nplanes) {
                float v;
                switch (j) {
                    case 0: v = a0.x; break;
                    case 1: v = a0.y; break;
                    case 2: v = a0.z; break;
                    case 3: v = a0.w; break;
                    case 4: v = a1.x; break;
                    case 5: v = a1.y; break;
                    case 6: v = a1.z; break;
                    default: v = a1.w; break;
                }
                out[gp * NPOS + p] = v;
            }
        }
    }
}

extern "C" void kernel_launch(void* const* d_in, const int* in_sizes, int n_in,
                              void* d_out, int out_size)
{
    const float* x      = (const float*)d_in[0];   // [32,64,19,19]
    const float* weight = (const float*)d_in[1];   // [2,18]
    float* out          = (float*)d_out;

    const int nplanes = in_sizes[0] / NPOS;        // 2048
    const int grid = (nplanes + PLANES_PER_BLOCK - 1) / PLANES_PER_BLOCK;

    raycast_kernel<<<grid, THREADS>>>(x, weight, out, nplanes);
}

// round 3
// speedup vs baseline: 1.1032x; 1.1032x over previous
#include <cuda_runtime.h>
#include <cuda_bf16.h>
#include <stdint.h>

// RayCastLayer via Toeplitz line-transform factorization.
// out = V + H + D1 + D2, each a dense 19-tap transform along its line family:
//   V : out[y][x] += sum_k WL[y][k] * s[k][x]
//   H : out[y][x] += sum_k WL[x][k] * s[y][k]
//   D1: out[y][x] += sum_k WD[y][k] * s[k][x+(k-y)]   (dirs (-1,-1),(1,1))
//   D2: out[y][x] += sum_k WD[y][k] * s[k][x-(k-y)]   (dirs (-1,1),(1,-1))
// WL/WD are 19x19 symmetric Toeplitz built from `weight`, zero diagonal.
// Off-board diagonal taps read lateral zero-padding (tile width 55).
// 8 planes per CTA stored as two float4 streams; FFMA2 (fma.rn.f32x2) packs
// 2 planes per FMA; each thread register-tiles 4 outputs along its line.

#define BOARD 19
#define NPOS  361
#define PW    55            // padded tile width (x shifted by +18)
#define TILE  (BOARD * PW)  // 1045 float4 entries per 4-plane stream
#define PLANES_PER_BLOCK 8
#define THREADS 416

// group layout (warp aligned): V [0,96) H [96,192) D1 [192,304) D2 [304,416)

__device__ __forceinline__ uint32_t smem_addr(const void* p) {
    return (uint32_t)__cvta_generic_to_shared(p);
}

// One line-transform pass: 19 k-steps, 4 outputs x 8 planes accumulated.
// STRIDE (in float4 units) is compile-time -> LDS immediate offsets.
template <int STRIDE>
__device__ __forceinline__ void pass_accum(uint32_t a0, uint32_t a1, uint32_t aw,
                                           unsigned long long acc[16])
{
    #pragma unroll
    for (int k = 0; k < BOARD; k++) {
        unsigned long long v0a, v0b, v1a, v1b;
        asm volatile("ld.shared.v2.b64 {%0,%1}, [%2];"
                     : "=l"(v0a), "=l"(v0b) : "r"(a0 + k * (STRIDE * 16)));
        asm volatile("ld.shared.v2.b64 {%0,%1}, [%2];"
                     : "=l"(v1a), "=l"(v1b) : "r"(a1 + k * (STRIDE * 16)));
        float w0, w1, w2, w3;
        asm volatile("ld.shared.v4.f32 {%0,%1,%2,%3}, [%4];"
                     : "=f"(w0), "=f"(w1), "=f"(w2), "=f"(w3)
                     : "r"(aw + k * 80));
        #pragma unroll
        for (int r = 0; r < 4; r++) {
            const float wr = (r == 0) ? w0 : (r == 1) ? w1 : (r == 2) ? w2 : w3;
            unsigned long long wp;
            const uint32_t wb = __float_as_uint(wr);
            asm volatile("mov.b64 %0, {%1,%1};" : "=l"(wp) : "r"(wb));
            asm volatile("fma.rn.f32x2 %0, %1, %2, %0;" : "+l"(acc[r*4+0]) : "l"(v0a), "l"(wp));
            asm volatile("fma.rn.f32x2 %0, %1, %2, %0;" : "+l"(acc[r*4+1]) : "l"(v0b), "l"(wp));
            asm volatile("fma.rn.f32x2 %0, %1, %2, %0;" : "+l"(acc[r*4+2]) : "l"(v1a), "l"(wp));
            asm volatile("fma.rn.f32x2 %0, %1, %2, %0;" : "+l"(acc[r*4+3]) : "l"(v1b), "l"(wp));
        }
    }
}

__global__ __launch_bounds__(THREADS, 2)
void raycast_kernel(const float* __restrict__ x,
                    const float* __restrict__ weight,
                    float* __restrict__ out,
                    int nplanes)
{
    __shared__ float4 t0[TILE];                 // planes 0..3, padded [19][55]
    __shared__ float4 t1[TILE];                 // planes 4..7
    __shared__ ulonglong2 o0[NPOS];             // out planes 0..3 (as 2x f32x2)
    __shared__ ulonglong2 o1[NPOS];             // out planes 4..7
    __shared__ __align__(16) float wlt[BOARD * 20];  // WL transposed: [k][y], y padded to 20
    __shared__ __align__(16) float wdt[BOARD * 20];  // WD transposed

    const int tid = threadIdx.x;
    const int g0  = blockIdx.x * PLANES_PER_BLOCK;

    // ---- build weight Toeplitz matrices (transposed, zero diag, zero pad col) ----
    for (int i = tid; i < BOARD * 20; i += THREADS) {
        const int k = i / 20;
        const int y = i - k * 20;
        const int d = (k > y) ? (k - y) : (y - k);
        const bool v = (y < BOARD) && (d > 0);
        wlt[i] = v ? weight[d - 1]      : 0.0f;
        wdt[i] = v ? weight[18 + d - 1] : 0.0f;
    }

    // ---- zero padded tiles ----
    const float4 z4 = make_float4(0.f, 0.f, 0.f, 0.f);
    for (int i = tid; i < TILE; i += THREADS) { t0[i] = z4; t1[i] = z4; }
    __syncthreads();

    // ---- load 8 planes into padded, transposed-by-plane layout ----
    float* t0f = reinterpret_cast<float*>(t0);
    float* t1f = reinterpret_cast<float*>(t1);
    for (int i = tid; i < PLANES_PER_BLOCK * NPOS; i += THREADS) {
        const int j  = i / NPOS;
        const int p  = i - j * NPOS;
        const int yy = p / BOARD;
        const int xx = p - yy * BOARD;
        const int gp = g0 + j;
        const float v = (gp < nplanes) ? x[gp * NPOS + p] : 0.0f;
        const int f = yy * PW + xx + 18;
        if (j < 4) t0f[f * 4 + j]       = v;
        else       t1f[f * 4 + (j - 4)] = v;
    }
    __syncthreads();

    const uint32_t t0a = smem_addr(t0);
    const uint32_t t1a = smem_addr(t1);
    const uint32_t wla = smem_addr(wlt);
    const uint32_t wda = smem_addr(wdt);

    unsigned long long acc[16];
    #pragma unroll
    for (int i = 0; i < 16; i++) acc[i] = 0ull;

    int  pr[4];
    bool vl[4];
    #pragma unroll
    for (int r = 0; r < 4; r++) { pr[r] = 0; vl[r] = false; }

    // ---- compute: warp-aligned group specialization ----
    if (tid < 96) {                          // V: outputs (y0+r, x), reads s[k][x]
        if (tid < 95) {
            const int yg = tid / BOARD;
            const int xx = tid - yg * BOARD;
            const int y0 = 4 * yg;
            pass_accum<PW>(t0a + (xx + 18) * 16, t1a + (xx + 18) * 16,
                           wla + y0 * 4, acc);
            #pragma unroll
            for (int r = 0; r < 4; r++) {
                const int yy = y0 + r;
                pr[r] = yy * BOARD + xx;
                vl[r] = (yy < BOARD);
            }
        }
    } else if (tid < 192) {                  // H: outputs (y, x0+r), reads s[y][k]
        const int gt = tid - 96;
        if (gt < 95) {
            const int yy = gt / 5;           // y slow -> conflict-free column strides
            const int xg = gt - yy * 5;
            const int x0 = 4 * xg;
            const int b  = yy * PW + 18;
            pass_accum<1>(t0a + b * 16, t1a + b * 16, wla + x0 * 4, acc);
            #pragma unroll
            for (int r = 0; r < 4; r++) {
                const int xx = x0 + r;
                pr[r] = yy * BOARD + xx;
                vl[r] = (xx < BOARD);
            }
        }
    } else if (tid < 304) {                  // D1: outputs (y0+r, xb+r), reads s[k][xb+k-y0]
        const int gt = tid - 192;
        if (gt < 110) {
            const int yg = gt / 22;
            const int xb = (gt - yg * 22) - 3;
            const int y0 = 4 * yg;
            int b = xb - y0 + 18;
            if (b < 0) b = 0;                // only the fully-invalid corner tile
            pass_accum<PW + 1>(t0a + b * 16, t1a + b * 16, wda + y0 * 4, acc);
            #pragma unroll
            for (int r = 0; r < 4; r++) {
                const int yy = y0 + r;
                const int xx = xb + r;
                pr[r] = yy * BOARD + xx;
                vl[r] = (yy < BOARD) && (xx >= 0) && (xx < BOARD);
            }
        }
    } else {                                 // D2: outputs (y0+r, xb-r), reads s[k][xb+y0-k... base-k]
        const int gt = tid - 304;
        if (gt < 110) {
            const int yg = gt / 22;
            const int xb = gt - yg * 22;     // 0..21
            const int y0 = 4 * yg;
            const int b  = xb + y0 + 18;
            pass_accum<PW - 1>(t0a + b * 16, t1a + b * 16, wda + y0 * 4, acc);
            #pragma unroll
            for (int r = 0; r < 4; r++) {
                const int yy = y0 + r;
                const int xx = xb - r;
                pr[r] = yy * BOARD + xx;
                vl[r] = (yy < BOARD) && (xx >= 0) && (xx < BOARD);
            }
        }
    }

    // ---- combine the 4 passes into smem output (race-free phases) ----
    // phase 0: V writes (covers every position exactly once)
    if (tid < 96) {
        #pragma unroll
        for (int r = 0; r < 4; r++) {
            if (vl[r]) {
                o0[pr[r]] = make_ulonglong2(acc[r*4+0], acc[r*4+1]);
                o1[pr[r]] = make_ulonglong2(acc[r*4+2], acc[r*4+3]);
            }
        }
    }
    __syncthreads();
    // phase 1: H accumulates
    if (tid >= 96 && tid < 192) {
        #pragma unroll
        for (int r = 0; r < 4; r++) {
            if (vl[r]) {
                ulonglong2 c0 = o0[pr[r]];
                ulonglong2 c1 = o1[pr[r]];
                asm volatile("add.rn.f32x2 %0, %0, %1;" : "+l"(acc[r*4+0]) : "l"(c0.x));
                asm volatile("add.rn.f32x2 %0, %0, %1;" : "+l"(acc[r*4+1]) : "l"(c0.y));
                asm volatile("add.rn.f32x2 %0, %0, %1;" : "+l"(acc[r*4+2]) : "l"(c1.x));
                asm volatile("add.rn.f32x2 %0, %0, %1;" : "+l"(acc[r*4+3]) : "l"(c1.y));
                o0[pr[r]] = make_ulonglong2(acc[r*4+0], acc[r*4+1]);
                o1[pr[r]] = make_ulonglong2(acc[r*4+2], acc[r*4+3]);
            }
        }
    }
    __syncthreads();
    // phase 2: D1 accumulates
    if (tid >= 192 && tid < 304) {
        #pragma unroll
        for (int r = 0; r < 4; r++) {
            if (vl[r]) {
                ulonglong2 c0 = o0[pr[r]];
                ulonglong2 c1 = o1[pr[r]];
                asm volatile("add.rn.f32x2 %0, %0, %1;" : "+l"(acc[r*4+0]) : "l"(c0.x));
                asm volatile("add.rn.f32x2 %0, %0, %1;" : "+l"(acc[r*4+1]) : "l"(c0.y));
                asm volatile("add.rn.f32x2 %0, %0, %1;" : "+l"(acc[r*4+2]) : "l"(c1.x));
                asm volatile("add.rn.f32x2 %0, %0, %1;" : "+l"(acc[r*4+3]) : "l"(c1.y));
                o0[pr[r]] = make_ulonglong2(acc[r*4+0], acc[r*4+1]);
                o1[pr[r]] = make_ulonglong2(acc[r*4+2], acc[r*4+3]);
            }
        }
    }
    __syncthreads();
    // phase 3: D2 accumulates
    if (tid >= 304) {
        #pragma unroll
        for (int r = 0; r < 4; r++) {
            if (vl[r]) {
                ulonglong2 c0 = o0[pr[r]];
                ulonglong2 c1 = o1[pr[r]];
                asm volatile("add.rn.f32x2 %0, %0, %1;" : "+l"(acc[r*4+0]) : "l"(c0.x));
                asm volatile("add.rn.f32x2 %0, %0, %1;" : "+l"(acc[r*4+1]) : "l"(c0.y));
                asm volatile("add.rn.f32x2 %0, %0, %1;" : "+l"(acc[r*4+2]) : "l"(c1.x));
                asm volatile("add.rn.f32x2 %0, %0, %1;" : "+l"(acc[r*4+3]) : "l"(c1.y));
                o0[pr[r]] = make_ulonglong2(acc[r*4+0], acc[r*4+1]);
                o1[pr[r]] = make_ulonglong2(acc[r*4+2], acc[r*4+3]);
            }
        }
    }
    __syncthreads();

    // ---- write out, coalesced per plane ----
    const float* of0 = reinterpret_cast<const float*>(o0);
    const float* of1 = reinterpret_cast<const float*>(o1);
    for (int i = tid; i < PLANES_PER_BLOCK * NPOS; i += THREADS) {
        const int j  = i / NPOS;
        const int p  = i - j * NPOS;
        const int gp = g0 + j;
        if (gp < nplanes) {
            const float v = (j < 4) ? of0[p * 4 + j] : of1[p * 4 + (j - 4)];
            out[gp * NPOS + p] = v;
        }
    }
}

extern "C" void kernel_launch(void* const* d_in, const int* in_sizes, int n_in,
                              void* d_out, int out_size)
{
    const float* x      = (const float*)d_in[0];   // [32,64,19,19]
    const float* weight = (const float*)d_in[1];   // [2,18]
    float* out          = (float*)d_out;

    const int nplanes = in_sizes[0] / NPOS;        // 2048
    const int grid = (nplanes + PLANES_PER_BLOCK - 1) / PLANES_PER_BLOCK;

    raycast_kernel<<<grid, THREADS>>>(x, weight, out, nplanes);
}

// round 4
// speedup vs baseline: 1.1528x; 1.0449x over previous
#include <cuda_runtime.h>
#include <cuda_bf16.h>
#include <stdint.h>

// RayCastLayer via Toeplitz line-transform factorization (R4: occupancy round).
// out = V + H + D1 + D2, each a dense 19-tap transform along its line family.
// 4 planes per CTA (float4 stream), FFMA2 packs 2 planes/instr, each thread
// register-tiles 4 outputs along its line. 4 partial smem buffers + 1 sync.

#define BOARD 19
#define NPOS  361
#define PW    55            // padded tile width (x shifted by +18)
#define TILE  (BOARD * PW)  // 1045 float4 entries
#define PLANES 4
#define THREADS 416

// group layout (warp aligned): V [0,96) H [96,192) D1 [192,304) D2 [304,416)

__device__ __forceinline__ uint32_t smem_addr(const void* p) {
    return (uint32_t)__cvta_generic_to_shared(p);
}

// One line-transform pass: 19 k-steps, 4 outputs x 4 planes accumulated.
// STRIDE (in float4 units) is compile-time -> LDS immediate offsets.
template <int STRIDE>
__device__ __forceinline__ void pass4(uint32_t a0, uint32_t aw,
                                      unsigned long long acc[8])
{
    #pragma unroll
    for (int k = 0; k < BOARD; k++) {
        unsigned long long v0a, v0b;
        asm volatile("ld.shared.v2.b64 {%0,%1}, [%2];"
                     : "=l"(v0a), "=l"(v0b) : "r"(a0 + k * (STRIDE * 16)));
        float w0, w1, w2, w3;
        asm volatile("ld.shared.v4.f32 {%0,%1,%2,%3}, [%4];"
                     : "=f"(w0), "=f"(w1), "=f"(w2), "=f"(w3)
                     : "r"(aw + k * 80));
        #pragma unroll
        for (int r = 0; r < 4; r++) {
            const float wr = (r == 0) ? w0 : (r == 1) ? w1 : (r == 2) ? w2 : w3;
            unsigned long long wp;
            const uint32_t wb = __float_as_uint(wr);
            asm("mov.b64 %0, {%1,%1};" : "=l"(wp) : "r"(wb));
            asm("fma.rn.f32x2 %0, %1, %2, %0;" : "+l"(acc[r*2+0]) : "l"(v0a), "l"(wp));
            asm("fma.rn.f32x2 %0, %1, %2, %0;" : "+l"(acc[r*2+1]) : "l"(v0b), "l"(wp));
        }
    }
}

__global__ __launch_bounds__(THREADS, 3)
void raycast_kernel(const float* __restrict__ x,
                    const float* __restrict__ weight,
                    float* __restrict__ out,
                    int nplanes)
{
    __shared__ float4 t0[TILE];                  // planes 0..3, padded [19][55]
    __shared__ ulonglong2 ov[NPOS];              // per-family partials
    __shared__ ulonglong2 oh[NPOS];
    __shared__ ulonglong2 od1[NPOS];
    __shared__ ulonglong2 od2[NPOS];
    __shared__ __align__(16) float wlt[BOARD * 20];  // WL^T: [k][y], y padded to 20
    __shared__ __align__(16) float wdt[BOARD * 20];  // WD^T

    const int tid = threadIdx.x;
    const int g0  = blockIdx.x * PLANES;

    // ---- build weight Toeplitz matrices (transposed, zero diag, zero pad col) ----
    for (int i = tid; i < BOARD * 20; i += THREADS) {
        const int k = i / 20;
        const int y = i - k * 20;
        const int d = (k > y) ? (k - y) : (y - k);
        const bool v = (y < BOARD) && (d > 0);
        wlt[i] = v ? weight[d - 1]      : 0.0f;
        wdt[i] = v ? weight[18 + d - 1] : 0.0f;
    }

    // ---- zero padded tile ----
    const float4 z4 = make_float4(0.f, 0.f, 0.f, 0.f);
    for (int i = tid; i < TILE; i += THREADS) t0[i] = z4;
    __syncthreads();

    // ---- load 4 planes into padded, transposed-by-plane layout ----
    float* t0f = reinterpret_cast<float*>(t0);
    for (int i = tid; i < PLANES * NPOS; i += THREADS) {
        const int j  = i / NPOS;
        const int p  = i - j * NPOS;
        const int yy = p / BOARD;
        const int xx = p - yy * BOARD;
        const int gp = g0 + j;
        const float v = (gp < nplanes) ? x[gp * NPOS + p] : 0.0f;
        t0f[(yy * PW + xx + 18) * 4 + j] = v;
    }
    __syncthreads();

    const uint32_t t0a = smem_addr(t0);
    const uint32_t wla = smem_addr(wlt);
    const uint32_t wda = smem_addr(wdt);

    unsigned long long acc[8];
    #pragma unroll
    for (int i = 0; i < 8; i++) acc[i] = 0ull;

    // ---- compute: warp-aligned group specialization; each family writes its
    //      own partial buffer (every board position covered exactly once) ----
    if (tid < 96) {                          // V: outputs (y0+r, x), reads s[k][x]
        if (tid < 95) {
            const int yg = tid / BOARD;
            const int xx = tid - yg * BOARD;
            const int y0 = 4 * yg;
            pass4<PW>(t0a + (xx + 18) * 16, wla + y0 * 4, acc);
            #pragma unroll
            for (int r = 0; r < 4; r++) {
                const int yy = y0 + r;
                if (yy < BOARD)
                    ov[yy * BOARD + xx] = make_ulonglong2(acc[r*2+0], acc[r*2+1]);
            }
        }
    } else if (tid < 192) {                  // H: outputs (y, x0+r), reads s[y][k]
        const int gt = tid - 96;
        if (gt < 95) {
            const int yy = gt / 5;           // y slow -> conflict-friendly strides
            const int xg = gt - yy * 5;
            const int x0 = 4 * xg;
            pass4<1>(t0a + (yy * PW + 18) * 16, wla + x0 * 4, acc);
            #pragma unroll
            for (int r = 0; r < 4; r++) {
                const int xx = x0 + r;
                if (xx < BOARD)
                    oh[yy * BOARD + xx] = make_ulonglong2(acc[r*2+0], acc[r*2+1]);
            }
        }
    } else if (tid < 304) {                  // D1: outputs (y0+r, xb+r)
        const int gt = tid - 192;
        if (gt < 110) {
            const int yg = gt / 22;
            const int xb = (gt - yg * 22) - 3;
            const int y0 = 4 * yg;
            int b = xb - y0 + 18;
            if (b < 0) b = 0;                // only the fully-invalid corner tile
            pass4<PW + 1>(t0a + b * 16, wda + y0 * 4, acc);
            #pragma unroll
            for (int r = 0; r < 4; r++) {
                const int yy = y0 + r;
                const int xx = xb + r;
                if ((yy < BOARD) && (xx >= 0) && (xx < BOARD))
                    od1[yy * BOARD + xx] = make_ulonglong2(acc[r*2+0], acc[r*2+1]);
            }
        }
    } else {                                 // D2: outputs (y0+r, xb-r)
        const int gt = tid - 304;
        if (gt < 110) {
            const int yg = gt / 22;
            const int xb = gt - yg * 22;     // 0..21
            const int y0 = 4 * yg;
            const int b  = xb + y0 + 18;
            pass4<PW - 1>(t0a + b * 16, wda + y0 * 4, acc);
            #pragma unroll
            for (int r = 0; r < 4; r++) {
                const int yy = y0 + r;
                const int xx = xb - r;
                if ((yy < BOARD) && (xx >= 0) && (xx < BOARD))
                    od2[yy * BOARD + xx] = make_ulonglong2(acc[r*2+0], acc[r*2+1]);
            }
        }
    }

    __syncthreads();

    // ---- combine 4 partials and store (coalesced per plane) ----
    if (tid < NPOS) {
        const ulonglong2 A = ov[tid];
        const ulonglong2 B = oh[tid];
        const ulonglong2 C = od1[tid];
        const ulonglong2 D = od2[tid];
        unsigned long long s0 = A.x, s1 = A.y;
        asm("add.rn.f32x2 %0, %0, %1;" : "+l"(s0) : "l"(B.x));
        asm("add.rn.f32x2 %0, %0, %1;" : "+l"(s0) : "l"(C.x));
        asm("add.rn.f32x2 %0, %0, %1;" : "+l"(s0) : "l"(D.x));
        asm("add.rn.f32x2 %0, %0, %1;" : "+l"(s1) : "l"(B.y));
        asm("add.rn.f32x2 %0, %0, %1;" : "+l"(s1) : "l"(C.y));
        asm("add.rn.f32x2 %0, %0, %1;" : "+l"(s1) : "l"(D.y));
        uint32_t p0, p1, p2, p3;
        asm("mov.b64 {%0,%1}, %2;" : "=r"(p0), "=r"(p1) : "l"(s0));
        asm("mov.b64 {%0,%1}, %2;" : "=r"(p2), "=r"(p3) : "l"(s1));
        const float v[4] = { __uint_as_float(p0), __uint_as_float(p1),
                             __uint_as_float(p2), __uint_as_float(p3) };
        #pragma unroll
        for (int j = 0; j < PLANES; j++) {
            const int gp = g0 + j;
            if (gp < nplanes) out[gp * NPOS + tid] = v[j];
        }
    }
}

extern "C" void kernel_launch(void* const* d_in, const int* in_sizes, int n_in,
                              void* d_out, int out_size)
{
    const float* x      = (const float*)d_in[0];   // [32,64,19,19]
    const float* weight = (const float*)d_in[1];   // [2,18]
    float* out          = (float*)d_out;

    const int nplanes = in_sizes[0] / NPOS;        // 2048
    const int grid = (nplanes + PLANES - 1) / PLANES;   // 512

    raycast_kernel<<<grid, THREADS>>>(x, weight, out, nplanes);
}